// round 1
// baseline (speedup 1.0000x reference)
#include <cuda_runtime.h>
#include <math.h>

// VectorQuantizer: z_e (16,256,1024) f32, emb (8192,256) f32
// out = [ quantized (16,256,1024), vq_loss, perplexity ]  (f32, concatenated)

#define Bv 16
#define Dv 256
#define Tv 1024
#define Kv 8192
#define Nv 16384            // B*T
#define BDT (Bv*Dv*Tv)      // 4194304

// ---------------- device scratch (no allocs allowed) ----------------
__device__ __align__(16) float g_h[Kv];     // 0.5*||e_k||^2
__device__ __align__(16) float g_xsq[Nv];   // ||x_n||^2
__device__ __align__(16) float g_m[Nv];     // max_k (x.e - 0.5||e||^2)
__device__ __align__(16) int   g_idx[Nv];   // argmax index
__device__ __align__(16) float g_cnt[Kv];   // histogram

// ---------------- codebook half-norms: h[k] = 0.5 * sum_d e[k][d]^2 ----------------
__global__ void k_norms(const float* __restrict__ emb) {
    int w = threadIdx.x >> 5, lane = threadIdx.x & 31;
    int k = blockIdx.x * 8 + w;                     // 1024 blocks * 8 warps
    const float4* row = (const float4*)(emb + (size_t)k * Dv);
    float s = 0.f;
#pragma unroll
    for (int i = 0; i < 2; i++) {
        float4 v = row[lane + 32 * i];
        s += v.x * v.x + v.y * v.y + v.z * v.z + v.w * v.w;
    }
#pragma unroll
    for (int o = 16; o; o >>= 1) s += __shfl_xor_sync(0xffffffffu, s, o);
    if (lane == 0) g_h[k] = 0.5f * s;
}

// ---------------- row squared-norms: xsq[n] = sum_d z_e[b,d,t]^2 ----------------
__global__ void k_xsq(const float* __restrict__ z) {
    int b = blockIdx.x >> 2;                 // 64 blocks: 16 b * 4 t-chunks
    int t0 = (blockIdx.x & 3) * 256;
    const float* p = z + (size_t)b * Dv * Tv + t0 + threadIdx.x;
    float s = 0.f;
#pragma unroll 8
    for (int d = 0; d < Dv; d++) { float v = p[(size_t)d * Tv]; s += v * v; }
    g_xsq[b * Tv + t0 + threadIdx.x] = s;
}

// ---------------- zero histogram (graph replays need explicit reset) ----------------
__global__ void k_zero() {
    g_cnt[blockIdx.x * 256 + threadIdx.x] = 0.f;
}

// ---------------- main fused GEMM + argmax ----------------
// CTA: 64 rows (one b, 64 consecutive t), sweep all K in tiles of 128.
// smem: xs_t[256][64] (x transposed, resident whole kernel) + es[32][132] (emb chunk, d-major).
// threads 256 = (cx 0..15) x (ry 0..15); thread tile = 4 rows x 8 cols.
#define SMEM_MAIN ((Dv * 64 + 32 * 132) * 4)

__global__ __launch_bounds__(256, 2) void k_main(const float* __restrict__ z,
                                                 const float* __restrict__ emb) {
    extern __shared__ float sm[];
    float* xs = sm;               // [256][64]
    float* es = sm + Dv * 64;     // [32][132]
    const int tid = threadIdx.x;
    const int n0 = blockIdx.x * 64;
    const int b = n0 >> 10, t0 = n0 & 1023;

    // stage x tile transposed: xs[d][j] = z_e[b, d, t0+j]
    const float* zb = z + (size_t)b * Dv * Tv + t0;
    for (int i = tid; i < Dv * 64; i += 256) {
        int d = i >> 6, j = i & 63;
        xs[i] = zb[(size_t)d * Tv + j];
    }
    __syncthreads();

    const int cx = tid & 15, ry = tid >> 4;
    const int dd4 = tid & 7, c0 = tid >> 3;

    float bestv[4]; int bestk[4];
#pragma unroll
    for (int i = 0; i < 4; i++) { bestv[i] = -3.4e38f; bestk[i] = 0; }

    // register prefetch of the first emb chunk
    float4 pf[4];
    {
        const float* g = emb + (size_t)c0 * Dv + dd4 * 4;
#pragma unroll
        for (int it = 0; it < 4; it++) pf[it] = *(const float4*)(g + (size_t)it * 32 * Dv);
    }

    for (int k0 = 0; k0 < Kv; k0 += 128) {
        float acc[4][8];
#pragma unroll
        for (int i = 0; i < 4; i++)
#pragma unroll
            for (int j = 0; j < 8; j++) acc[i][j] = 0.f;

        for (int d0 = 0; d0 < Dv; d0 += 32) {
            // store prefetched chunk, transposed: es[dd][c]
#pragma unroll
            for (int it = 0; it < 4; it++) {
                int c = c0 + 32 * it;
                es[(dd4 * 4 + 0) * 132 + c] = pf[it].x;
                es[(dd4 * 4 + 1) * 132 + c] = pf[it].y;
                es[(dd4 * 4 + 2) * 132 + c] = pf[it].z;
                es[(dd4 * 4 + 3) * 132 + c] = pf[it].w;
            }
            __syncthreads();

            // prefetch next chunk (hides L2 latency behind the FMA block)
            int nd0 = d0 + 32, nk0 = k0;
            if (nd0 == Dv) { nd0 = 0; nk0 += 128; }
            if (nk0 < Kv) {
                const float* g = emb + (size_t)(nk0 + c0) * Dv + nd0 + dd4 * 4;
#pragma unroll
                for (int it = 0; it < 4; it++) pf[it] = *(const float4*)(g + (size_t)it * 32 * Dv);
            }

            const float* xp  = xs + d0 * 64 + ry * 4;
            const float* esp = es + cx * 8;
#pragma unroll 8
            for (int dd = 0; dd < 32; dd++) {
                float4 av = *(const float4*)(xp + dd * 64);
                float4 b0 = *(const float4*)(esp + dd * 132);
                float4 b1 = *(const float4*)(esp + dd * 132 + 4);
                float aa[4] = { av.x, av.y, av.z, av.w };
                float bb[8] = { b0.x, b0.y, b0.z, b0.w, b1.x, b1.y, b1.z, b1.w };
#pragma unroll
                for (int i = 0; i < 4; i++)
#pragma unroll
                    for (int j = 0; j < 8; j++)
                        acc[i][j] = fmaf(aa[i], bb[j], acc[i][j]);
            }
            __syncthreads();
        }

        // epilogue: per-row argmax of (score - h) over this 128-col tile
        float4 h0 = *(const float4*)(g_h + k0 + cx * 8);
        float4 h1 = *(const float4*)(g_h + k0 + cx * 8 + 4);
        float hv[8] = { h0.x, h0.y, h0.z, h0.w, h1.x, h1.y, h1.z, h1.w };
#pragma unroll
        for (int i = 0; i < 4; i++) {
            float v = acc[i][0] - hv[0];
            int kk = k0 + cx * 8;
#pragma unroll
            for (int j = 1; j < 8; j++) {
                float w = acc[i][j] - hv[j];
                int kj = k0 + cx * 8 + j;
                if (w > v || (w == v && kj < kk)) { v = w; kk = kj; }
            }
#pragma unroll
            for (int o = 8; o; o >>= 1) {   // 16-lane butterfly (cx groups)
                float ov = __shfl_xor_sync(0xffffffffu, v, o);
                int   ok = __shfl_xor_sync(0xffffffffu, kk, o);
                if (ov > v || (ov == v && ok < kk)) { v = ov; kk = ok; }
            }
            if (v > bestv[i] || (v == bestv[i] && kk < bestk[i])) { bestv[i] = v; bestk[i] = kk; }
        }
    }

    if (cx == 0) {
#pragma unroll
        for (int i = 0; i < 4; i++) {
            int n = n0 + ry * 4 + i;
            g_m[n]   = bestv[i];
            g_idx[n] = bestk[i];
        }
    }
}

// ---------------- histogram ----------------
__global__ void k_hist() {
    int n = blockIdx.x * 256 + threadIdx.x;
    atomicAdd(&g_cnt[g_idx[n]], 1.0f);
}

// ---------------- scatter codebook rows to (b,d,t) layout via smem transpose ----------------
__global__ void k_scatter(const float* __restrict__ emb, float* __restrict__ out) {
    __shared__ float tile[32][257];
    __shared__ int sidx[32];
    int n0 = blockIdx.x * 32;                 // 512 blocks
    int b = n0 >> 10, t0 = n0 & 1023;
    if (threadIdx.x < 32) sidx[threadIdx.x] = g_idx[n0 + threadIdx.x];
    __syncthreads();
    for (int i = threadIdx.x; i < 32 * Dv; i += 256) {
        int r = i >> 8, d = i & 255;
        tile[r][d] = emb[(size_t)sidx[r] * Dv + d];   // coalesced emb row reads
    }
    __syncthreads();
    float* ob = out + (size_t)b * Dv * Tv + t0;
    for (int i = threadIdx.x; i < 32 * Dv; i += 256) {
        int d = i >> 5, r = i & 31;
        ob[(size_t)d * Tv + r] = tile[r][d];          // coalesced 128B stores
    }
}

// ---------------- scalars: vq_loss and perplexity ----------------
__global__ void k_final(float* __restrict__ out, int out_size) {
    __shared__ double sd[256];
    int tid = threadIdx.x;
    double s = 0.0;
    for (int n = tid; n < Nv; n += 256)
        s += (double)g_xsq[n] - 2.0 * (double)g_m[n];   // dist_n = ||x||^2 - 2*max
    double e = 0.0;
    for (int k = tid; k < Kv; k += 256) {
        double p = (double)g_cnt[k] * (1.0 / (double)Nv);
        e += p * log(p + 1e-10);
    }
    sd[tid] = s; __syncthreads();
    for (int o = 128; o; o >>= 1) { if (tid < o) sd[tid] += sd[tid + o]; __syncthreads(); }
    double loss = 0.25 * sd[0] / ((double)Nv * (double)Dv);
    __syncthreads();
    sd[tid] = e; __syncthreads();
    for (int o = 128; o; o >>= 1) { if (tid < o) sd[tid] += sd[tid + o]; __syncthreads(); }
    if (tid == 0 && out_size >= BDT + 2) {
        out[BDT]     = (float)loss;
        out[BDT + 1] = (float)exp(-sd[0]);
    }
}

// ---------------- launch ----------------
extern "C" void kernel_launch(void* const* d_in, const int* in_sizes, int n_in,
                              void* d_out, int out_size) {
    const float* z   = (const float*)d_in[0];   // z_e (16,256,1024)
    const float* emb = (const float*)d_in[1];   // emb (8192,256)
    float* out = (float*)d_out;

    cudaFuncSetAttribute(k_main, cudaFuncAttributeMaxDynamicSharedMemorySize, SMEM_MAIN);

    k_norms  <<<Kv / 8, 256>>>(emb);
    k_xsq    <<<64, 256>>>(z);
    k_zero   <<<Kv / 256, 256>>>();
    k_main   <<<Nv / 64, 256, SMEM_MAIN>>>(z, emb);
    k_hist   <<<Nv / 256, 256>>>();
    k_scatter<<<Nv / 32, 256>>>(emb, out);
    k_final  <<<1, 256>>>(out, out_size);
}

// round 2
// speedup vs baseline: 1.7160x; 1.7160x over previous
#include <cuda_runtime.h>
#include <math.h>

// VectorQuantizer: z_e (16,256,1024) f32, emb (8192,256) f32
// out = [ quantized (16,256,1024), vq_loss, perplexity ]  (f32, concatenated)

#define Bv 16
#define Dv 256
#define Tv 1024
#define Kv 8192
#define Nv 16384            // B*T
#define BDT (Bv*Dv*Tv)      // 4194304

// ---------------- device scratch (no allocs allowed) ----------------
__device__ __align__(16) float g_h[Kv];     // 0.5*||e_k||^2
__device__ __align__(16) float g_xsq[Nv];   // ||x_n||^2
__device__ __align__(16) float g_m[Nv];     // max_k (x.e - 0.5||e||^2)
__device__ __align__(16) int   g_idx[Nv];   // argmax index
__device__ __align__(16) float g_cnt[Kv];   // histogram

// ---------------- codebook half-norms ----------------
__global__ void k_norms(const float* __restrict__ emb) {
    int w = threadIdx.x >> 5, lane = threadIdx.x & 31;
    int k = blockIdx.x * 8 + w;
    const float4* row = (const float4*)(emb + (size_t)k * Dv);
    float s = 0.f;
#pragma unroll
    for (int i = 0; i < 2; i++) {
        float4 v = row[lane + 32 * i];
        s += v.x * v.x + v.y * v.y + v.z * v.z + v.w * v.w;
    }
#pragma unroll
    for (int o = 16; o; o >>= 1) s += __shfl_xor_sync(0xffffffffu, s, o);
    if (lane == 0) g_h[k] = 0.5f * s;
}

// ---------------- row squared-norms ----------------
__global__ void k_xsq(const float* __restrict__ z) {
    int b = blockIdx.x >> 2;
    int t0 = (blockIdx.x & 3) * 256;
    const float* p = z + (size_t)b * Dv * Tv + t0 + threadIdx.x;
    float s = 0.f;
#pragma unroll 8
    for (int d = 0; d < Dv; d++) { float v = p[(size_t)d * Tv]; s += v * v; }
    g_xsq[b * Tv + t0 + threadIdx.x] = s;
}

// ---------------- zero histogram ----------------
__global__ void k_zero() {
    g_cnt[blockIdx.x * 256 + threadIdx.x] = 0.f;
}

// ---------------- main fused GEMM + argmax ----------------
// CTA: 128 rows (one b, 128 consecutive t), sweeps all K in 64 tiles of 128 cols.
// x tile resident in smem as[256][128] (loaded once, f4-coalesced since d-rows are
// contiguous in t). emb chunk double-buffered bs[2][16][132].
// 256 threads = (tx 0..15) x (ty 0..15); thread tile 8 rows x 8 cols (4+4 split).
#define SMEM_MAIN (Dv * 128 * 4 + 2 * 16 * 132 * 4)

__global__ __launch_bounds__(256, 1) void k_main(const float* __restrict__ z,
                                                 const float* __restrict__ emb) {
    extern __shared__ float sm[];
    float* as = sm;               // [256][128]  (d-major)
    float* bs = sm + Dv * 128;    // [2][16][132]
    const int tid = threadIdx.x;
    const int n0 = blockIdx.x * 128;
    const int b = n0 >> 10, t0 = n0 & 1023;
    const int tx = tid & 15, ty = tid >> 4;

    // stage x tile: as[d][n] = z_e[b, d, t0+n]   (coalesced float4 along t)
    const float* zb = z + (size_t)b * (Dv * Tv) + t0;
    for (int f = tid; f < Dv * 32; f += 256) {
        int d = f >> 5, nq = f & 31;
        *(float4*)(as + d * 128 + nq * 4) = *(const float4*)(zb + (size_t)d * Tv + nq * 4);
    }

    const int cB = tid >> 2;     // base col 0..63 (r=1 adds 64)
    const int qB = tid & 3;      // d-quad within chunk

    // prefetch first emb chunk (k0=0, d0=0)
    float4 pb[2];
    {
        const float* g = emb + (size_t)cB * Dv + qB * 4;
        pb[0] = *(const float4*)(g);
        pb[1] = *(const float4*)(g + (size_t)64 * Dv);
    }

    float bestv[8]; int bestk[8];
#pragma unroll
    for (int i = 0; i < 8; i++) { bestv[i] = -3.4e38f; bestk[i] = 0; }

    __syncthreads();   // as ready

    int p = 0;
    for (int k0 = 0; k0 < Kv; k0 += 128) {
        float acc[8][8];
#pragma unroll
        for (int i = 0; i < 8; i++)
#pragma unroll
            for (int j = 0; j < 8; j++) acc[i][j] = 0.f;

#pragma unroll 1
        for (int c = 0; c < 16; c++) {
            float* bw = bs + p * (16 * 132);
            // store prefetched chunk transposed: bw[dd][col]
#pragma unroll
            for (int r = 0; r < 2; r++) {
                int col = cB + 64 * r;
                float4 v = pb[r];
                bw[(qB * 4 + 0) * 132 + col] = v.x;
                bw[(qB * 4 + 1) * 132 + col] = v.y;
                bw[(qB * 4 + 2) * 132 + col] = v.z;
                bw[(qB * 4 + 3) * 132 + col] = v.w;
            }
            __syncthreads();

            // prefetch next chunk into registers (hides L2 latency)
            int nc = c + 1, nk = k0;
            if (nc == 16) { nc = 0; nk += 128; }
            if (nk < Kv) {
                const float* g = emb + (size_t)(nk + cB) * Dv + nc * 16 + qB * 4;
                pb[0] = *(const float4*)(g);
                pb[1] = *(const float4*)(g + (size_t)64 * Dv);
            }

            const float* ap = as + (c * 16) * 128 + ty * 4;
            const float* bp = bw + tx * 4;
#pragma unroll
            for (int dd = 0; dd < 16; dd++) {
                float4 a0 = *(const float4*)(ap + dd * 128);
                float4 a1 = *(const float4*)(ap + dd * 128 + 64);
                float4 b0 = *(const float4*)(bp + dd * 132);
                float4 b1 = *(const float4*)(bp + dd * 132 + 64);
                float aa[8] = { a0.x, a0.y, a0.z, a0.w, a1.x, a1.y, a1.z, a1.w };
                float bb[8] = { b0.x, b0.y, b0.z, b0.w, b1.x, b1.y, b1.z, b1.w };
#pragma unroll
                for (int i = 0; i < 8; i++)
#pragma unroll
                    for (int j = 0; j < 8; j++)
                        acc[i][j] = fmaf(aa[i], bb[j], acc[i][j]);
            }
            p ^= 1;
        }

        // epilogue: per-row argmax of (score - h) over this 128-col tile
        float4 h0 = *(const float4*)(g_h + k0 + tx * 4);
        float4 h1 = *(const float4*)(g_h + k0 + 64 + tx * 4);
        float hv[8] = { h0.x, h0.y, h0.z, h0.w, h1.x, h1.y, h1.z, h1.w };
        int   kc[8];
#pragma unroll
        for (int j = 0; j < 4; j++) { kc[j] = k0 + tx * 4 + j; kc[4 + j] = k0 + 64 + tx * 4 + j; }
#pragma unroll
        for (int i = 0; i < 8; i++) {
            float v = acc[i][0] - hv[0];
            int kk = kc[0];
#pragma unroll
            for (int j = 1; j < 8; j++) {
                float w = acc[i][j] - hv[j];
                if (w > v || (w == v && kc[j] < kk)) { v = w; kk = kc[j]; }
            }
#pragma unroll
            for (int o = 8; o; o >>= 1) {   // reduce across tx (16 lanes)
                float ov = __shfl_xor_sync(0xffffffffu, v, o);
                int   ok = __shfl_xor_sync(0xffffffffu, kk, o);
                if (ov > v || (ov == v && ok < kk)) { v = ov; kk = ok; }
            }
            if (v > bestv[i] || (v == bestv[i] && kk < bestk[i])) { bestv[i] = v; bestk[i] = kk; }
        }
    }

    if (tx == 0) {
#pragma unroll
        for (int i = 0; i < 8; i++) {
            int r = ty * 4 + (i & 3) + ((i >> 2) << 6);
            int n = n0 + r;
            g_m[n]   = bestv[i];
            g_idx[n] = bestk[i];
        }
    }
}

// ---------------- histogram ----------------
__global__ void k_hist() {
    int n = blockIdx.x * 256 + threadIdx.x;
    atomicAdd(&g_cnt[g_idx[n]], 1.0f);
}

// ---------------- scatter codebook rows to (b,d,t) layout ----------------
__global__ void k_scatter(const float* __restrict__ emb, float* __restrict__ out) {
    __shared__ float tile[32][257];
    __shared__ int sidx[32];
    int n0 = blockIdx.x * 32;
    int b = n0 >> 10, t0 = n0 & 1023;
    if (threadIdx.x < 32) sidx[threadIdx.x] = g_idx[n0 + threadIdx.x];
    __syncthreads();
    for (int i = threadIdx.x; i < 32 * Dv; i += 256) {
        int r = i >> 8, d = i & 255;
        tile[r][d] = emb[(size_t)sidx[r] * Dv + d];
    }
    __syncthreads();
    float* ob = out + (size_t)b * Dv * Tv + t0;
    for (int i = threadIdx.x; i < 32 * Dv; i += 256) {
        int d = i >> 5, r = i & 31;
        ob[(size_t)d * Tv + r] = tile[r][d];
    }
}

// ---------------- scalars: vq_loss and perplexity ----------------
__global__ void k_final(float* __restrict__ out, int out_size) {
    __shared__ double sd[256];
    int tid = threadIdx.x;
    double s = 0.0;
    for (int n = tid; n < Nv; n += 256)
        s += (double)g_xsq[n] - 2.0 * (double)g_m[n];
    double e = 0.0;
    for (int k = tid; k < Kv; k += 256) {
        double p = (double)g_cnt[k] * (1.0 / (double)Nv);
        e += p * log(p + 1e-10);
    }
    sd[tid] = s; __syncthreads();
    for (int o = 128; o; o >>= 1) { if (tid < o) sd[tid] += sd[tid + o]; __syncthreads(); }
    double loss = 0.25 * sd[0] / ((double)Nv * (double)Dv);
    __syncthreads();
    sd[tid] = e; __syncthreads();
    for (int o = 128; o; o >>= 1) { if (tid < o) sd[tid] += sd[tid + o]; __syncthreads(); }
    if (tid == 0 && out_size >= BDT + 2) {
        out[BDT]     = (float)loss;
        out[BDT + 1] = (float)exp(-sd[0]);
    }
}

// ---------------- launch ----------------
extern "C" void kernel_launch(void* const* d_in, const int* in_sizes, int n_in,
                              void* d_out, int out_size) {
    const float* z   = (const float*)d_in[0];   // z_e (16,256,1024)
    const float* emb = (const float*)d_in[1];   // emb (8192,256)
    float* out = (float*)d_out;

    cudaFuncSetAttribute(k_main, cudaFuncAttributeMaxDynamicSharedMemorySize, SMEM_MAIN);

    k_norms  <<<Kv / 8, 256>>>(emb);
    k_xsq    <<<64, 256>>>(z);
    k_zero   <<<Kv / 256, 256>>>();
    k_main   <<<Nv / 128, 256, SMEM_MAIN>>>(z, emb);
    k_hist   <<<Nv / 256, 256>>>();
    k_scatter<<<Nv / 32, 256>>>(emb, out);
    k_final  <<<1, 256>>>(out, out_size);
}

// round 4
// speedup vs baseline: 2.0640x; 1.2028x over previous
#include <cuda_runtime.h>
#include <cuda_bf16.h>
#include <cstdint>
#include <math.h>

// VectorQuantizer: z_e (16,256,1024) f32, emb (8192,256) f32
// out = [ quantized (16,256,1024), vq_loss, perplexity ]  (f32)

#define Bv 16
#define Dv 256
#define Tv 1024
#define Kv 8192
#define Nv 16384
#define BDT (Bv*Dv*Tv)

#define TAU 8e-3f

// ---------------- device scratch ----------------
__device__ __align__(16) __nv_bfloat16 g_xhi[(size_t)Nv * Dv];
__device__ __align__(16) __nv_bfloat16 g_xlo[(size_t)Nv * Dv];
__device__ __align__(16) float         g_xf [(size_t)Nv * Dv];
__device__ __align__(16) __nv_bfloat16 g_ehi[(size_t)Kv * Dv];
__device__ __align__(16) __nv_bfloat16 g_elo[(size_t)Kv * Dv];
__device__ __align__(16) float g_h[Kv];
__device__ __align__(16) float g_xsq[Nv];
__device__ __align__(16) float g_m[Nv];
__device__ __align__(16) int   g_idx[Nv];
__device__ __align__(16) float g_cnt[Kv];
__device__ int g_nflag;
__device__ __align__(16) int g_flags[Nv];

// ---------------- helpers ----------------
__device__ __forceinline__ uint32_t smem_u32(const void* p) {
    uint32_t a;
    asm("{ .reg .u64 t; cvta.to.shared.u64 t, %1; cvt.u32.u64 %0, t; }" : "=r"(a) : "l"(p));
    return a;
}
// SW128 swizzle (128B-period rows, 16B granularity)
#define SW(o) ((o) ^ ((((uint32_t)(o)) >> 3) & 0x70u))

#define LDMX4(r0, r1, r2, r3, a) \
    asm volatile("ldmatrix.sync.aligned.m8n8.x4.shared.b16 {%0,%1,%2,%3}, [%4];" \
        : "=r"(r0), "=r"(r1), "=r"(r2), "=r"(r3) : "r"(a))

#define MMA16816(c, a0, a1, a2, a3, b0, b1) \
    asm volatile("mma.sync.aligned.m16n8k16.row.col.f32.bf16.bf16.f32 " \
        "{%0,%1,%2,%3}, {%4,%5,%6,%7}, {%8,%9}, {%0,%1,%2,%3};" \
        : "+f"((c)[0]), "+f"((c)[1]), "+f"((c)[2]), "+f"((c)[3]) \
        : "r"(a0), "r"(a1), "r"(a2), "r"(a3), "r"(b0), "r"(b1))

// ---------------- prep: split emb into bf16 hi/lo + half norms ----------------
__global__ void k_split_e(const float* __restrict__ emb) {
    int w = threadIdx.x >> 5, lane = threadIdx.x & 31;
    int k = blockIdx.x * 8 + w;
    size_t o = (size_t)k * Dv + lane * 8;
    float4 a = *(const float4*)(emb + o);
    float4 b = *(const float4*)(emb + o + 4);
    float x[8] = { a.x, a.y, a.z, a.w, b.x, b.y, b.z, b.w };
    float s = 0.f;
    __nv_bfloat16 hi[8], lo[8];
#pragma unroll
    for (int i = 0; i < 8; i++) {
        s += x[i] * x[i];
        hi[i] = __float2bfloat16_rn(x[i]);
        lo[i] = __float2bfloat16_rn(x[i] - __bfloat162float(hi[i]));
    }
    *(uint4*)(g_ehi + o) = *(uint4*)hi;
    *(uint4*)(g_elo + o) = *(uint4*)lo;
#pragma unroll
    for (int t = 16; t; t >>= 1) s += __shfl_xor_sync(0xffffffffu, s, t);
    if (lane == 0) g_h[k] = 0.5f * s;
}

// ---------------- prep: transpose z (b,d,t) -> x[n][d] f32 + bf16 hi/lo ----------------
__global__ void k_split_x(const float* __restrict__ z) {
    __shared__ float tile[64][65];
    int t0 = blockIdx.x * 64, d0 = blockIdx.y * 64, b = blockIdx.z;
    const float* src = z + ((size_t)b * Dv + d0) * Tv + t0;
    for (int i = threadIdx.x; i < 1024; i += 256) {
        int dd = i >> 4, tq = i & 15;
        float4 v = *(const float4*)(src + (size_t)dd * Tv + tq * 4);
        tile[dd][tq * 4 + 0] = v.x; tile[dd][tq * 4 + 1] = v.y;
        tile[dd][tq * 4 + 2] = v.z; tile[dd][tq * 4 + 3] = v.w;
    }
    __syncthreads();
    int n0 = b * Tv + t0;
    for (int i = threadIdx.x; i < 1024; i += 256) {
        int tt = i >> 4, dq = i & 15;
        float y[4];
#pragma unroll
        for (int c = 0; c < 4; c++) y[c] = tile[dq * 4 + c][tt];
        size_t o = (size_t)(n0 + tt) * Dv + d0 + dq * 4;
        *(float4*)(g_xf + o) = make_float4(y[0], y[1], y[2], y[3]);
        __nv_bfloat16 hi[4], lo[4];
#pragma unroll
        for (int c = 0; c < 4; c++) {
            hi[c] = __float2bfloat16_rn(y[c]);
            lo[c] = __float2bfloat16_rn(y[c] - __bfloat162float(hi[c]));
        }
        *(uint2*)(g_xhi + o) = *(uint2*)hi;
        *(uint2*)(g_xlo + o) = *(uint2*)lo;
    }
}

__global__ void k_zero() {
    g_cnt[blockIdx.x * 256 + threadIdx.x] = 0.f;
    if (blockIdx.x == 0 && threadIdx.x == 0) g_nflag = 0;
}

// ---------------- main: ldmatrix + mma.sync bf16 3-term GEMM + fused argmax ----------------
// smem (from 1KB-aligned base):
//   [0, 64K)      A hi: 4 d-blocks x [128r][64d] bf16, SW128 per 128B row
//   [64K, 128K)   A lo
//   [128K, 144K)  B hi chunk [128n][64d]
//   [144K, 160K)  B lo chunk
#define SM_ALO 65536
#define SM_B   131072
#define SMEM_SZ (163840 + 1024)

__global__ __launch_bounds__(256, 1) void k_mma() {
    extern __shared__ char smraw[];
    uint32_t raw = smem_u32(smraw);
    uint32_t sb = (raw + 1023u) & ~1023u;
    char* smp = smraw + (sb - raw);
    const int tid = threadIdx.x, wid = tid >> 5, lane = tid & 31;
    const int n0 = blockIdx.x * 128;
    const int g = lane >> 2, tg = lane & 3;

    // stage A: Xhi/Xlo, 4 blocks of [128r][64 bf16] SW128
    for (int u = tid; u < 4096; u += 256) {
        int c = u >> 10, r = (u >> 3) & 127, q = u & 7;
        size_t so = (size_t)(n0 + r) * Dv + c * 64 + q * 8;
        uint32_t off = c * 16384 + SW(r * 128 + q * 16);
        *(uint4*)(smp + off)          = *(const uint4*)(g_xhi + so);
        *(uint4*)(smp + SM_ALO + off) = *(const uint4*)(g_xlo + so);
    }

    // per-lane ldmatrix address constants
    const int m = lane >> 3, j7 = lane & 7;
    const uint32_t arow = (uint32_t)(wid * 16 + (m & 1) * 8 + j7) * 128;
    const uint32_t ach  = (uint32_t)(lane >> 4) * 16;            // A col-half (16B)
    const uint32_t brow = (uint32_t)((m >> 1) * 8 + j7) * 128;   // B n-row
    const uint32_t bko  = (uint32_t)(m & 1) * 16;                // B k-half (16B)

    // prefetch first B chunk (kt=0, c=0)
    uint4 pfh[4], pfl[4];
#pragma unroll
    for (int i = 0; i < 4; i++) {
        int u = tid + 256 * i, row = u >> 3, q = u & 7;
        size_t so = (size_t)row * Dv + q * 8;
        pfh[i] = *(const uint4*)(g_ehi + so);
        pfl[i] = *(const uint4*)(g_elo + so);
    }
    __syncthreads();

    // trackers: 2 rows per thread (g, g+8 within warp stripe)
    float best[2]  = { -3.4e38f, -3.4e38f };
    float best2[2] = { -3.4e38f, -3.4e38f };
    int   bk[2]    = { 0, 0 };

#pragma unroll 1
    for (int kt = 0; kt < 64; kt++) {
        float acc[16][4];
#pragma unroll
        for (int i = 0; i < 16; i++)
#pragma unroll
            for (int q = 0; q < 4; q++) acc[i][q] = 0.f;

#pragma unroll 1
        for (int c = 0; c < 4; c++) {
            // store prefetched B chunk
#pragma unroll
            for (int i = 0; i < 4; i++) {
                int u = tid + 256 * i, row = u >> 3, q = u & 7;
                uint32_t off = SW(row * 128 + q * 16);
                *(uint4*)(smp + SM_B + off)         = pfh[i];
                *(uint4*)(smp + SM_B + 16384 + off) = pfl[i];
            }
            __syncthreads();

            // prefetch next chunk
            int nc = c + 1, nk = kt;
            if (nc == 4) { nc = 0; nk++; }
            if (nk < 64) {
#pragma unroll
                for (int i = 0; i < 4; i++) {
                    int u = tid + 256 * i, row = u >> 3, q = u & 7;
                    size_t so = (size_t)(nk * 128 + row) * Dv + nc * 64 + q * 8;
                    pfh[i] = *(const uint4*)(g_ehi + so);
                    pfl[i] = *(const uint4*)(g_elo + so);
                }
            }

            // compute: 4 k16-steps over this 64-d chunk
#pragma unroll
            for (int ds = 0; ds < 4; ds++) {
                uint32_t ax = arow + ds * 32 + ach;
                uint32_t aoff = sb + c * 16384 + SW(ax);
                uint32_t ah0, ah1, ah2, ah3, al0, al1, al2, al3;
                LDMX4(ah0, ah1, ah2, ah3, aoff);
                LDMX4(al0, al1, al2, al3, aoff + SM_ALO);
#pragma unroll
                for (int nt = 0; nt < 8; nt++) {
                    uint32_t bx = brow + nt * 2048 + ds * 32 + bko;
                    uint32_t boff = sb + SM_B + SW(bx);
                    uint32_t bh0, bh1, bh2, bh3, bl0, bl1, bl2, bl3;
                    LDMX4(bh0, bh1, bh2, bh3, boff);
                    LDMX4(bl0, bl1, bl2, bl3, boff + 16384);
                    MMA16816(acc[2 * nt],     ah0, ah1, ah2, ah3, bh0, bh1);
                    MMA16816(acc[2 * nt + 1], ah0, ah1, ah2, ah3, bh2, bh3);
                    MMA16816(acc[2 * nt],     ah0, ah1, ah2, ah3, bl0, bl1);
                    MMA16816(acc[2 * nt + 1], ah0, ah1, ah2, ah3, bl2, bl3);
                    MMA16816(acc[2 * nt],     al0, al1, al2, al3, bh0, bh1);
                    MMA16816(acc[2 * nt + 1], al0, al1, al2, al3, bh2, bh3);
                }
            }
            __syncthreads();
        }

        // epilogue: fold this 128-col tile into per-thread trackers
#pragma unroll
        for (int t = 0; t < 16; t++) {
            int col = kt * 128 + t * 8 + 2 * tg;
            float h0 = __ldg(g_h + col), h1 = __ldg(g_h + col + 1);
            float v00 = acc[t][0] - h0, v01 = acc[t][1] - h1;
            float v10 = acc[t][2] - h0, v11 = acc[t][3] - h1;
            if (v00 > best[0]) { best2[0] = best[0]; best[0] = v00; bk[0] = col; }
            else if (v00 > best2[0]) best2[0] = v00;
            if (v01 > best[0]) { best2[0] = best[0]; best[0] = v01; bk[0] = col + 1; }
            else if (v01 > best2[0]) best2[0] = v01;
            if (v10 > best[1]) { best2[1] = best[1]; best[1] = v10; bk[1] = col; }
            else if (v10 > best2[1]) best2[1] = v10;
            if (v11 > best[1]) { best2[1] = best[1]; best[1] = v11; bk[1] = col + 1; }
            else if (v11 > best2[1]) best2[1] = v11;
        }
    }

    // reduce across the 4 lanes (tg) sharing each row
#pragma unroll
    for (int r = 0; r < 2; r++) {
#pragma unroll
        for (int o = 1; o <= 2; o <<= 1) {
            float ob = __shfl_xor_sync(0xffffffffu, best[r], o);
            float os = __shfl_xor_sync(0xffffffffu, best2[r], o);
            int   ok = __shfl_xor_sync(0xffffffffu, bk[r], o);
            if (ob > best[r] || (ob == best[r] && ok < bk[r])) {
                best2[r] = fmaxf(best[r], os);
                best[r] = ob; bk[r] = ok;
            } else {
                best2[r] = fmaxf(best2[r], ob);
            }
        }
    }
    if (tg == 0) {
#pragma unroll
        for (int r = 0; r < 2; r++) {
            int n = n0 + wid * 16 + g + r * 8;
            g_idx[n] = bk[r];
            if (best[r] - best2[r] < TAU) {
                int p = atomicAdd(&g_nflag, 1);
                g_flags[p] = n;
            }
        }
    }
}

// ---------------- exact rescore of near-tie rows (full K, fp32) ----------------
__global__ void k_rescore(const float* __restrict__ emb) {
    __shared__ float sx[Dv];
    __shared__ float bv[8];
    __shared__ int   bki[8];
    int tid = threadIdx.x, w = tid >> 5, lane = tid & 31;
    int nf = g_nflag;
    for (int f = blockIdx.x; f < nf; f += gridDim.x) {
        int n = g_flags[f];
        sx[tid] = g_xf[(size_t)n * Dv + tid];
        __syncthreads();
        float best = -3.4e38f; int bk = 0;
        const float* xs = sx + lane * 8;
        for (int i = 0; i < 1024; i++) {
            int k = w * 1024 + i;
            const float* e = emb + (size_t)k * Dv + lane * 8;
            float4 e0 = *(const float4*)(e);
            float4 e1 = *(const float4*)(e + 4);
            float s = xs[0] * e0.x + xs[1] * e0.y + xs[2] * e0.z + xs[3] * e0.w
                    + xs[4] * e1.x + xs[5] * e1.y + xs[6] * e1.z + xs[7] * e1.w;
#pragma unroll
            for (int t = 16; t; t >>= 1) s += __shfl_xor_sync(0xffffffffu, s, t);
            if (lane == 0) {
                float v = s - g_h[k];
                if (v > best) { best = v; bk = k; }
            }
        }
        if (lane == 0) { bv[w] = best; bki[w] = bk; }
        __syncthreads();
        if (tid == 0) {
            float b = bv[0]; int k = bki[0];
            for (int ww = 1; ww < 8; ww++)
                if (bv[ww] > b || (bv[ww] == b && bki[ww] < k)) { b = bv[ww]; k = bki[ww]; }
            g_idx[n] = k;
        }
        __syncthreads();
    }
}

// ---------------- exact g_m + xsq for all rows (loss precision) ----------------
__global__ void k_exactm(const float* __restrict__ emb) {
    int w = threadIdx.x >> 5, lane = threadIdx.x & 31;
#pragma unroll 1
    for (int r = 0; r < 4; r++) {
        int n = blockIdx.x * 32 + w * 4 + r;
        int id = g_idx[n];
        const float* x = g_xf + (size_t)n * Dv + lane * 8;
        const float* e = emb + (size_t)id * Dv + lane * 8;
        float4 x0 = *(const float4*)(x), x1 = *(const float4*)(x + 4);
        float4 e0 = *(const float4*)(e), e1 = *(const float4*)(e + 4);
        float s = x0.x * e0.x + x0.y * e0.y + x0.z * e0.z + x0.w * e0.w
                + x1.x * e1.x + x1.y * e1.y + x1.z * e1.z + x1.w * e1.w;
        float q = x0.x * x0.x + x0.y * x0.y + x0.z * x0.z + x0.w * x0.w
                + x1.x * x1.x + x1.y * x1.y + x1.z * x1.z + x1.w * x1.w;
#pragma unroll
        for (int t = 16; t; t >>= 1) {
            s += __shfl_xor_sync(0xffffffffu, s, t);
            q += __shfl_xor_sync(0xffffffffu, q, t);
        }
        if (lane == 0) { g_m[n] = s - g_h[id]; g_xsq[n] = q; }
    }
}

// ---------------- histogram ----------------
__global__ void k_hist() {
    int n = blockIdx.x * 256 + threadIdx.x;
    atomicAdd(&g_cnt[g_idx[n]], 1.0f);
}

// ---------------- scatter codebook rows to (b,d,t) ----------------
__global__ void k_scatter(const float* __restrict__ emb, float* __restrict__ out) {
    __shared__ float tile[32][257];
    __shared__ int sidx[32];
    int n0 = blockIdx.x * 32;
    int b = n0 >> 10, t0 = n0 & 1023;
    if (threadIdx.x < 32) sidx[threadIdx.x] = g_idx[n0 + threadIdx.x];
    __syncthreads();
    for (int i = threadIdx.x; i < 32 * Dv; i += 256) {
        int r = i >> 8, d = i & 255;
        tile[r][d] = emb[(size_t)sidx[r] * Dv + d];
    }
    __syncthreads();
    float* ob = out + (size_t)b * Dv * Tv + t0;
    for (int i = threadIdx.x; i < 32 * Dv; i += 256) {
        int d = i >> 5, r = i & 31;
        ob[(size_t)d * Tv + r] = tile[r][d];
    }
}

// ---------------- scalars ----------------
__global__ void k_final(float* __restrict__ out, int out_size) {
    __shared__ double sd[256];
    int tid = threadIdx.x;
    double s = 0.0;
    for (int n = tid; n < Nv; n += 256)
        s += (double)g_xsq[n] - 2.0 * (double)g_m[n];
    double e = 0.0;
    for (int k = tid; k < Kv; k += 256) {
        double p = (double)g_cnt[k] * (1.0 / (double)Nv);
        e += p * log(p + 1e-10);
    }
    sd[tid] = s; __syncthreads();
    for (int o = 128; o; o >>= 1) { if (tid < o) sd[tid] += sd[tid + o]; __syncthreads(); }
    double loss = 0.25 * sd[0] / ((double)Nv * (double)Dv);
    __syncthreads();
    sd[tid] = e; __syncthreads();
    for (int o = 128; o; o >>= 1) { if (tid < o) sd[tid] += sd[tid + o]; __syncthreads(); }
    if (tid == 0 && out_size >= BDT + 2) {
        out[BDT]     = (float)loss;
        out[BDT + 1] = (float)exp(-sd[0]);
    }
}

// ---------------- launch ----------------
extern "C" void kernel_launch(void* const* d_in, const int* in_sizes, int n_in,
                              void* d_out, int out_size) {
    const float* z   = (const float*)d_in[0];
    const float* emb = (const float*)d_in[1];
    float* out = (float*)d_out;

    cudaFuncSetAttribute(k_mma, cudaFuncAttributeMaxDynamicSharedMemorySize, SMEM_SZ);

    k_split_e<<<Kv / 8, 256>>>(emb);
    k_split_x<<<dim3(Tv / 64, Dv / 64, Bv), 256>>>(z);
    k_zero   <<<Kv / 256, 256>>>();
    k_mma    <<<Nv / 128, 256, SMEM_SZ>>>();
    k_rescore<<<64, 256>>>(emb);
    k_exactm <<<Nv / 32, 256>>>(emb);
    k_hist   <<<Nv / 256, 256>>>();
    k_scatter<<<Nv / 32, 256>>>(emb, out);
    k_final  <<<1, 256>>>(out, out_size);
}

// round 5
// speedup vs baseline: 2.2708x; 1.1002x over previous
#include <cuda_runtime.h>
#include <cuda_bf16.h>
#include <cstdint>
#include <math.h>

// VectorQuantizer: z_e (16,256,1024) f32, emb (8192,256) f32
// out = [ quantized (16,256,1024), vq_loss, perplexity ]  (f32)

#define Bv 16
#define Dv 256
#define Tv 1024
#define Kv 8192
#define Nv 16384
#define BDT (Bv*Dv*Tv)

#define TAU 8e-3f

// ---------------- device scratch ----------------
__device__ __align__(16) __nv_bfloat16 g_xhi[(size_t)Nv * Dv];
__device__ __align__(16) __nv_bfloat16 g_xlo[(size_t)Nv * Dv];
__device__ __align__(16) float         g_xf [(size_t)Nv * Dv];
__device__ __align__(16) __nv_bfloat16 g_ehi[(size_t)Kv * Dv];
__device__ __align__(16) __nv_bfloat16 g_elo[(size_t)Kv * Dv];
__device__ __align__(16) float g_h[Kv];
__device__ __align__(16) float g_xsq[Nv];
__device__ __align__(16) float g_m[Nv];
__device__ __align__(16) int   g_idx[Nv];
__device__ __align__(16) float g_cnt[Kv];
__device__ int g_nflag;
__device__ __align__(16) int g_flags[Nv];

// ---------------- helpers ----------------
__device__ __forceinline__ uint32_t smem_u32(const void* p) {
    uint32_t a;
    asm("{ .reg .u64 t; cvta.to.shared.u64 t, %1; cvt.u32.u64 %0, t; }" : "=r"(a) : "l"(p));
    return a;
}
#define SW(o) ((o) ^ ((((uint32_t)(o)) >> 3) & 0x70u))

#define LDMX4(r, a) \
    asm volatile("ldmatrix.sync.aligned.m8n8.x4.shared.b16 {%0,%1,%2,%3}, [%4];" \
        : "=r"((r)[0]), "=r"((r)[1]), "=r"((r)[2]), "=r"((r)[3]) : "r"(a))

#define MMA16816(c, a, b0, b1) \
    asm volatile("mma.sync.aligned.m16n8k16.row.col.f32.bf16.bf16.f32 " \
        "{%0,%1,%2,%3}, {%4,%5,%6,%7}, {%8,%9}, {%0,%1,%2,%3};" \
        : "+f"((c)[0]), "+f"((c)[1]), "+f"((c)[2]), "+f"((c)[3]) \
        : "r"((a)[0]), "r"((a)[1]), "r"((a)[2]), "r"((a)[3]), "r"(b0), "r"(b1))

// ---------------- prep: split emb into bf16 hi/lo + half norms ----------------
__global__ void k_split_e(const float* __restrict__ emb) {
    int w = threadIdx.x >> 5, lane = threadIdx.x & 31;
    int k = blockIdx.x * 8 + w;
    size_t o = (size_t)k * Dv + lane * 8;
    float4 a = *(const float4*)(emb + o);
    float4 b = *(const float4*)(emb + o + 4);
    float x[8] = { a.x, a.y, a.z, a.w, b.x, b.y, b.z, b.w };
    float s = 0.f;
    __nv_bfloat16 hi[8], lo[8];
#pragma unroll
    for (int i = 0; i < 8; i++) {
        s += x[i] * x[i];
        hi[i] = __float2bfloat16_rn(x[i]);
        lo[i] = __float2bfloat16_rn(x[i] - __bfloat162float(hi[i]));
    }
    *(uint4*)(g_ehi + o) = *(uint4*)hi;
    *(uint4*)(g_elo + o) = *(uint4*)lo;
#pragma unroll
    for (int t = 16; t; t >>= 1) s += __shfl_xor_sync(0xffffffffu, s, t);
    if (lane == 0) g_h[k] = 0.5f * s;
}

// ---------------- prep: transpose z (b,d,t) -> x[n][d] f32 + bf16 hi/lo ----------------
__global__ void k_split_x(const float* __restrict__ z) {
    __shared__ float tile[64][65];
    int t0 = blockIdx.x * 64, d0 = blockIdx.y * 64, b = blockIdx.z;
    const float* src = z + ((size_t)b * Dv + d0) * Tv + t0;
    for (int i = threadIdx.x; i < 1024; i += 256) {
        int dd = i >> 4, tq = i & 15;
        float4 v = *(const float4*)(src + (size_t)dd * Tv + tq * 4);
        tile[dd][tq * 4 + 0] = v.x; tile[dd][tq * 4 + 1] = v.y;
        tile[dd][tq * 4 + 2] = v.z; tile[dd][tq * 4 + 3] = v.w;
    }
    __syncthreads();
    int n0 = b * Tv + t0;
    for (int i = threadIdx.x; i < 1024; i += 256) {
        int tt = i >> 4, dq = i & 15;
        float y[4];
#pragma unroll
        for (int c = 0; c < 4; c++) y[c] = tile[dq * 4 + c][tt];
        size_t o = (size_t)(n0 + tt) * Dv + d0 + dq * 4;
        *(float4*)(g_xf + o) = make_float4(y[0], y[1], y[2], y[3]);
        __nv_bfloat16 hi[4], lo[4];
#pragma unroll
        for (int c = 0; c < 4; c++) {
            hi[c] = __float2bfloat16_rn(y[c]);
            lo[c] = __float2bfloat16_rn(y[c] - __bfloat162float(hi[c]));
        }
        *(uint2*)(g_xhi + o) = *(uint2*)hi;
        *(uint2*)(g_xlo + o) = *(uint2*)lo;
    }
}

__global__ void k_zero() {
    g_cnt[blockIdx.x * 256 + threadIdx.x] = 0.f;
    if (blockIdx.x == 0 && threadIdx.x == 0) g_nflag = 0;
}

// ---------------- main: ldmatrix + mma.sync bf16 3-term GEMM + fused argmax ----------------
// Warp w: stripe-pair sp=w>>1 (rows sp*32..sp*32+31), n-half nh=w&1 (cols nh*64..+63).
// smem: A hi [0,64K) 4 blocks x [128r][64d] SW128; A lo [64K,128K);
//       B double buffer [128K,192K): 2 x (hi 16K + lo 16K).
#define SM_ALO 65536
#define SM_B   131072
#define SMEM_SZ (196608 + 1024)

__global__ __launch_bounds__(256, 1) void k_mma() {
    extern __shared__ char smraw[];
    uint32_t raw = smem_u32(smraw);
    uint32_t sb = (raw + 1023u) & ~1023u;
    char* smp = smraw + (sb - raw);
    const int tid = threadIdx.x, wid = tid >> 5, lane = tid & 31;
    const int n0 = blockIdx.x * 128;
    const int sp = wid >> 1, nh = wid & 1;
    const int g = lane >> 2, tg = lane & 3;

    // stage A: Xhi/Xlo, 4 blocks of [128r][64 bf16] SW128
    for (int u = tid; u < 4096; u += 256) {
        int c = u >> 10, r = (u >> 3) & 127, q = u & 7;
        size_t so = (size_t)(n0 + r) * Dv + c * 64 + q * 8;
        uint32_t off = c * 16384 + SW(r * 128 + q * 16);
        *(uint4*)(smp + off)          = *(const uint4*)(g_xhi + so);
        *(uint4*)(smp + SM_ALO + off) = *(const uint4*)(g_xlo + so);
    }

    // ldmatrix lane-address constants
    const int m = lane >> 3, j7 = lane & 7;
    uint32_t arow[2];
#pragma unroll
    for (int s = 0; s < 2; s++)
        arow[s] = (uint32_t)(sp * 32 + s * 16 + (m & 1) * 8 + j7) * 128;
    const uint32_t ach  = (uint32_t)(lane >> 4) * 16;
    const uint32_t bbase = (uint32_t)(nh * 64 + (m >> 1) * 8 + j7) * 128 + (uint32_t)(m & 1) * 16;

    // prefetch first B chunk (kt=0, c=0)
    uint4 pfh[4], pfl[4];
#pragma unroll
    for (int i = 0; i < 4; i++) {
        int u = tid + 256 * i, row = u >> 3, q = u & 7;
        size_t so = (size_t)row * Dv + q * 8;
        pfh[i] = *(const uint4*)(g_ehi + so);
        pfl[i] = *(const uint4*)(g_elo + so);
    }
    __syncthreads();

    // trackers: 4 rows per thread: r = s*2+rh -> row sp*32 + s*16 + g + rh*8
    float best[4]  = { -3.4e38f, -3.4e38f, -3.4e38f, -3.4e38f };
    float best2[4] = { -3.4e38f, -3.4e38f, -3.4e38f, -3.4e38f };
    int   bk[4]    = { 0, 0, 0, 0 };

    int p = 0;
#pragma unroll 1
    for (int kt = 0; kt < 64; kt++) {
        float acc[16][4];
#pragma unroll
        for (int i = 0; i < 16; i++)
#pragma unroll
            for (int q = 0; q < 4; q++) acc[i][q] = 0.f;

#pragma unroll 1
        for (int c = 0; c < 4; c++) {
            // store prefetched B chunk into buf p
            char* bb = smp + SM_B + p * 32768;
#pragma unroll
            for (int i = 0; i < 4; i++) {
                int u = tid + 256 * i, row = u >> 3, q = u & 7;
                uint32_t off = SW(row * 128 + q * 16);
                *(uint4*)(bb + off)         = pfh[i];
                *(uint4*)(bb + 16384 + off) = pfl[i];
            }
            __syncthreads();

            // prefetch next chunk
            int nc = c + 1, nk = kt;
            if (nc == 4) { nc = 0; nk++; }
            if (nk < 64) {
#pragma unroll
                for (int i = 0; i < 4; i++) {
                    int u = tid + 256 * i, row = u >> 3, q = u & 7;
                    size_t so = (size_t)(nk * 128 + row) * Dv + nc * 64 + q * 8;
                    pfh[i] = *(const uint4*)(g_ehi + so);
                    pfl[i] = *(const uint4*)(g_elo + so);
                }
            }

            const uint32_t abase = sb + c * 16384;
            const uint32_t bB = sb + SM_B + p * 32768;
#pragma unroll
            for (int ds = 0; ds < 4; ds++) {
                uint32_t A[2][2][4];   // [stripe][hi/lo]
#pragma unroll
                for (int s = 0; s < 2; s++) {
                    uint32_t ao = abase + SW(arow[s] + ds * 32 + ach);
                    LDMX4(A[s][0], ao);
                    LDMX4(A[s][1], ao + SM_ALO);
                }
                uint32_t Bf[2][8];     // double buffer: [0..3]=hi, [4..7]=lo
                {
                    uint32_t bo = bB + SW(bbase + ds * 32);
                    LDMX4(Bf[0], bo);
                    LDMX4(Bf[0] + 4, bo + 16384);
                }
#pragma unroll
                for (int nt = 0; nt < 4; nt++) {
                    if (nt < 3) {
                        uint32_t bo = bB + SW(bbase + (nt + 1) * 2048 + ds * 32);
                        LDMX4(Bf[(nt + 1) & 1], bo);
                        LDMX4(Bf[(nt + 1) & 1] + 4, bo + 16384);
                    }
                    const uint32_t* B = Bf[nt & 1];
#pragma unroll
                    for (int s = 0; s < 2; s++) {
                        float* a0 = acc[(s * 4 + nt) * 2];
                        float* a1 = acc[(s * 4 + nt) * 2 + 1];
                        MMA16816(a0, A[s][0], B[0], B[1]);
                        MMA16816(a1, A[s][0], B[2], B[3]);
                        MMA16816(a0, A[s][0], B[4], B[5]);
                        MMA16816(a1, A[s][0], B[6], B[7]);
                        MMA16816(a0, A[s][1], B[0], B[1]);
                        MMA16816(a1, A[s][1], B[2], B[3]);
                    }
                }
            }
            p ^= 1;
        }

        // epilogue: fold this 128-col tile into per-thread trackers
#pragma unroll
        for (int s = 0; s < 2; s++)
#pragma unroll
            for (int nt = 0; nt < 4; nt++)
#pragma unroll
                for (int j = 0; j < 2; j++) {
                    int t = (s * 4 + nt) * 2 + j;
                    int col = kt * 128 + nh * 64 + nt * 16 + j * 8 + 2 * tg;
                    float h0 = __ldg(g_h + col), h1 = __ldg(g_h + col + 1);
                    int r0 = s * 2, r1 = s * 2 + 1;
                    float v00 = acc[t][0] - h0, v01 = acc[t][1] - h1;
                    float v10 = acc[t][2] - h0, v11 = acc[t][3] - h1;
                    if (v00 > best[r0]) { best2[r0] = best[r0]; best[r0] = v00; bk[r0] = col; }
                    else if (v00 > best2[r0]) best2[r0] = v00;
                    if (v01 > best[r0]) { best2[r0] = best[r0]; best[r0] = v01; bk[r0] = col + 1; }
                    else if (v01 > best2[r0]) best2[r0] = v01;
                    if (v10 > best[r1]) { best2[r1] = best[r1]; best[r1] = v10; bk[r1] = col; }
                    else if (v10 > best2[r1]) best2[r1] = v10;
                    if (v11 > best[r1]) { best2[r1] = best[r1]; best[r1] = v11; bk[r1] = col + 1; }
                    else if (v11 > best2[r1]) best2[r1] = v11;
                }
    }

    // reduce across the 4 lanes (tg) sharing each row
#pragma unroll
    for (int r = 0; r < 4; r++) {
#pragma unroll
        for (int o = 1; o <= 2; o <<= 1) {
            float ob = __shfl_xor_sync(0xffffffffu, best[r], o);
            float os = __shfl_xor_sync(0xffffffffu, best2[r], o);
            int   ok = __shfl_xor_sync(0xffffffffu, bk[r], o);
            if (ob > best[r] || (ob == best[r] && ok < bk[r])) {
                best2[r] = fmaxf(best[r], os);
                best[r] = ob; bk[r] = ok;
            } else {
                best2[r] = fmaxf(best2[r], ob);
            }
        }
    }

    // cross-warp (n-half) merge via smem
    __syncthreads();
    float* fb = (float*)smp;           // [2][128] best
    float* fs = fb + 256;              // [2][128] best2
    int*   fk = (int*)(fs + 256);      // [2][128] idx
    if (tg == 0) {
#pragma unroll
        for (int r = 0; r < 4; r++) {
            int row = sp * 32 + (r >> 1) * 16 + g + (r & 1) * 8;
            fb[nh * 128 + row] = best[r];
            fs[nh * 128 + row] = best2[r];
            fk[nh * 128 + row] = bk[r];
        }
    }
    __syncthreads();
    if (tid < 128) {
        float b0 = fb[tid], b1 = fb[128 + tid];
        float s0 = fs[tid], s1 = fs[128 + tid];
        int   k0 = fk[tid], k1 = fk[128 + tid];
        float bb, ss; int kk;
        if (b0 > b1 || (b0 == b1 && k0 < k1)) { bb = b0; kk = k0; ss = fmaxf(s0, b1); }
        else                                   { bb = b1; kk = k1; ss = fmaxf(s1, b0); }
        int n = n0 + tid;
        g_idx[n] = kk;
        if (bb - ss < TAU) {
            int pos = atomicAdd(&g_nflag, 1);
            g_flags[pos] = n;
        }
    }
}

// ---------------- exact rescore of near-tie rows (full K, fp32) ----------------
__global__ void k_rescore(const float* __restrict__ emb) {
    __shared__ float sx[Dv];
    __shared__ float bv[8];
    __shared__ int   bki[8];
    int tid = threadIdx.x, w = tid >> 5, lane = tid & 31;
    int nf = g_nflag;
    for (int f = blockIdx.x; f < nf; f += gridDim.x) {
        int n = g_flags[f];
        sx[tid] = g_xf[(size_t)n * Dv + tid];
        __syncthreads();
        float best = -3.4e38f; int bk = 0;
        const float* xs = sx + lane * 8;
        for (int i = 0; i < 1024; i++) {
            int k = w * 1024 + i;
            const float* e = emb + (size_t)k * Dv + lane * 8;
            float4 e0 = *(const float4*)(e);
            float4 e1 = *(const float4*)(e + 4);
            float s = xs[0] * e0.x + xs[1] * e0.y + xs[2] * e0.z + xs[3] * e0.w
                    + xs[4] * e1.x + xs[5] * e1.y + xs[6] * e1.z + xs[7] * e1.w;
#pragma unroll
            for (int t = 16; t; t >>= 1) s += __shfl_xor_sync(0xffffffffu, s, t);
            if (lane == 0) {
                float v = s - g_h[k];
                if (v > best) { best = v; bk = k; }
            }
        }
        if (lane == 0) { bv[w] = best; bki[w] = bk; }
        __syncthreads();
        if (tid == 0) {
            float b = bv[0]; int k = bki[0];
            for (int ww = 1; ww < 8; ww++)
                if (bv[ww] > b || (bv[ww] == b && bki[ww] < k)) { b = bv[ww]; k = bki[ww]; }
            g_idx[n] = k;
        }
        __syncthreads();
    }
}

// ---------------- exact g_m + xsq + histogram ----------------
__global__ void k_exactm(const float* __restrict__ emb) {
    int w = threadIdx.x >> 5, lane = threadIdx.x & 31;
#pragma unroll 1
    for (int r = 0; r < 4; r++) {
        int n = blockIdx.x * 32 + w * 4 + r;
        int id = g_idx[n];
        const float* x = g_xf + (size_t)n * Dv + lane * 8;
        const float* e = emb + (size_t)id * Dv + lane * 8;
        float4 x0 = *(const float4*)(x), x1 = *(const float4*)(x + 4);
        float4 e0 = *(const float4*)(e), e1 = *(const float4*)(e + 4);
        float s = x0.x * e0.x + x0.y * e0.y + x0.z * e0.z + x0.w * e0.w
                + x1.x * e1.x + x1.y * e1.y + x1.z * e1.z + x1.w * e1.w;
        float q = x0.x * x0.x + x0.y * x0.y + x0.z * x0.z + x0.w * x0.w
                + x1.x * x1.x + x1.y * x1.y + x1.z * x1.z + x1.w * x1.w;
#pragma unroll
        for (int t = 16; t; t >>= 1) {
            s += __shfl_xor_sync(0xffffffffu, s, t);
            q += __shfl_xor_sync(0xffffffffu, q, t);
        }
        if (lane == 0) {
            g_m[n] = s - g_h[id];
            g_xsq[n] = q;
            atomicAdd(&g_cnt[id], 1.0f);
        }
    }
}

// ---------------- scatter codebook rows to (b,d,t) ----------------
__global__ void k_scatter(const float* __restrict__ emb, float* __restrict__ out) {
    __shared__ float tile[32][257];
    __shared__ int sidx[32];
    int n0 = blockIdx.x * 32;
    int b = n0 >> 10, t0 = n0 & 1023;
    if (threadIdx.x < 32) sidx[threadIdx.x] = g_idx[n0 + threadIdx.x];
    __syncthreads();
    for (int i = threadIdx.x; i < 32 * Dv; i += 256) {
        int r = i >> 8, d = i & 255;
        tile[r][d] = emb[(size_t)sidx[r] * Dv + d];
    }
    __syncthreads();
    float* ob = out + (size_t)b * Dv * Tv + t0;
    for (int i = threadIdx.x; i < 32 * Dv; i += 256) {
        int d = i >> 5, r = i & 31;
        ob[(size_t)d * Tv + r] = tile[r][d];
    }
}

// ---------------- scalars ----------------
__global__ void k_final(float* __restrict__ out, int out_size) {
    __shared__ double sd[256];
    int tid = threadIdx.x;
    double s = 0.0;
    for (int n = tid; n < Nv; n += 256)
        s += (double)g_xsq[n] - 2.0 * (double)g_m[n];
    double e = 0.0;
    for (int k = tid; k < Kv; k += 256) {
        double p = (double)g_cnt[k] * (1.0 / (double)Nv);
        e += p * log(p + 1e-10);
    }
    sd[tid] = s; __syncthreads();
    for (int o = 128; o; o >>= 1) { if (tid < o) sd[tid] += sd[tid + o]; __syncthreads(); }
    double loss = 0.25 * sd[0] / ((double)Nv * (double)Dv);
    __syncthreads();
    sd[tid] = e; __syncthreads();
    for (int o = 128; o; o >>= 1) { if (tid < o) sd[tid] += sd[tid + o]; __syncthreads(); }
    if (tid == 0 && out_size >= BDT + 2) {
        out[BDT]     = (float)loss;
        out[BDT + 1] = (float)exp(-sd[0]);
    }
}

// ---------------- launch ----------------
extern "C" void kernel_launch(void* const* d_in, const int* in_sizes, int n_in,
                              void* d_out, int out_size) {
    const float* z   = (const float*)d_in[0];
    const float* emb = (const float*)d_in[1];
    float* out = (float*)d_out;

    cudaFuncSetAttribute(k_mma, cudaFuncAttributeMaxDynamicSharedMemorySize, SMEM_SZ);

    k_split_e<<<Kv / 8, 256>>>(emb);
    k_split_x<<<dim3(Tv / 64, Dv / 64, Bv), 256>>>(z);
    k_zero   <<<Kv / 256, 256>>>();
    k_mma    <<<Nv / 128, 256, SMEM_SZ>>>();
    k_rescore<<<128, 256>>>(emb);
    k_exactm <<<Nv / 32, 256>>>(emb);
    k_scatter<<<Nv / 32, 256>>>(emb, out);
    k_final  <<<1, 256>>>(out, out_size);
}